// round 5
// baseline (speedup 1.0000x reference)
#include <cuda_runtime.h>
#include <math.h>
#include <stdint.h>

// Problem shape (fixed for this dataset instance)
constexpr int Bb = 4;
constexpr int Tt = 4096;
constexpr int Dd = 2048;
constexpr int BT = Bb * Tt;           // 16384 rows
constexpr float EPS = 1e-5f;

// Scan chunking
constexpr int NC = 32;
constexpr int CH = Tt / NC;           // 128

// Shared GEMM geometry
constexpr int BK = 16;
constexpr int LDA_S = 20;             // padded floats per A row
constexpr int A_FLOATS = 128 * LDA_S; // 2560

// Dual (i+f) kernel: BM=128, per-matrix BN=128
constexpr int LDB_D = 136;
constexpr int BD_FLOATS = BK * LDB_D;                    // 2176
constexpr int STG_D = A_FLOATS + 2 * BD_FLOATS;          // 6912
constexpr int SMEM_D = 4 * STG_D * 4;                    // 110592 B

// Wide kernel: BM=128, BN=256
constexpr int LDB_W = 264;
constexpr int BW_FLOATS = BK * LDB_W;                    // 4224
constexpr int STG_W = A_FLOATS + BW_FLOATS;              // 6784
constexpr int SMEM_W = 4 * STG_W * 4;                    // 108544 B

// Scratch (device globals — no allocation allowed)
__device__ float g_a   [(size_t)BT * Dd];      // sigmoid(f)
__device__ float g_inp [(size_t)BT * Dd];      // silu(i)*(1-a)
__device__ float g_gg  [(size_t)BT * Dd];      // silu(g)
__device__ float g_o   [(size_t)BT * Dd];
__device__ float g_u   [(size_t)BT * Dd];
__device__ float g_xr  [(size_t)BT * Dd];
__device__ float g_wr  [(size_t)4 * Dd * Dd];
__device__ float g_cA  [(size_t)Bb * NC * Dd];
__device__ float g_cH  [(size_t)Bb * NC * Dd];
__device__ float g_cIn [(size_t)Bb * NC * Dd];

// ---------------------------------------------------------------------------
__device__ __forceinline__ float tf32r(float x) {
    uint32_t u;
    asm("cvt.rna.tf32.f32 %0, %1;" : "=r"(u) : "f"(x));
    return __uint_as_float(u);
}

__device__ __forceinline__ void cp16(uint32_t dst, const void* src) {
    asm volatile("cp.async.cg.shared.global [%0], [%1], 16;\n" :: "r"(dst), "l"(src));
}

__device__ __forceinline__ void mma1688(float* d, const uint32_t* a, const uint32_t* b) {
    asm volatile(
        "mma.sync.aligned.m16n8k8.row.col.f32.tf32.tf32.f32 "
        "{%0,%1,%2,%3}, {%4,%5,%6,%7}, {%8,%9}, {%0,%1,%2,%3};"
        : "+f"(d[0]), "+f"(d[1]), "+f"(d[2]), "+f"(d[3])
        : "r"(a[0]), "r"(a[1]), "r"(a[2]), "r"(a[3]), "r"(b[0]), "r"(b[1]));
}

__device__ __forceinline__ float sigm(float v) { return 1.0f / (1.0f + __expf(-v)); }

// ---------------------------------------------------------------------------
__global__ void round_tf32_kernel(const float* __restrict__ in,
                                  float* __restrict__ out, int n4)
{
    int i = blockIdx.x * blockDim.x + threadIdx.x;
    if (i < n4) {
        float4 v = reinterpret_cast<const float4*>(in)[i];
        v.x = tf32r(v.x); v.y = tf32r(v.y); v.z = tf32r(v.z); v.w = tf32r(v.w);
        reinterpret_cast<float4*>(out)[i] = v;
    }
}

// ---------------------------------------------------------------------------
// Fused i/f GEMM + gate epilogue.
// aOut = sigmoid(x*Wf), inpOut = silu(x*Wi) * (1 - aOut).
// CTA tile 128(M)x128(N), both matrices. 8 warps (2m x 4n), warp 64x32/matrix.
// ---------------------------------------------------------------------------
__global__ __launch_bounds__(256, 1)
void gemm_if(const float* __restrict__ A, const float* __restrict__ Bi,
             const float* __restrict__ Bf, float* __restrict__ aOut,
             float* __restrict__ inpOut, int M, int N, int K)
{
    extern __shared__ float smem[];

    const int tid  = threadIdx.x;
    const int warp = tid >> 5;
    const int lane = tid & 31;
    const int wm   = warp >> 2;
    const int wn   = warp & 3;
    const int gid  = lane >> 2;
    const int tig  = lane & 3;
    const int m0   = blockIdx.y * 128;
    const int n0   = blockIdx.x * 128;

    float acci[4][4][4], accf[4][4][4];
#pragma unroll
    for (int i = 0; i < 4; i++)
#pragma unroll
        for (int j = 0; j < 4; j++)
#pragma unroll
            for (int r = 0; r < 4; r++) { acci[i][j][r] = 0.0f; accf[i][j][r] = 0.0f; }

    const uint32_t smem_b = (uint32_t)__cvta_generic_to_shared(smem);

    auto load_stage = [&](int kt, int s) {
        const int k0 = kt * BK;
        const uint32_t sa  = smem_b + s * STG_D * 4;
        const uint32_t sb0 = sa + A_FLOATS * 4;
        const uint32_t sb1 = sb0 + BD_FLOATS * 4;
#pragma unroll
        for (int i = 0; i < 2; i++) {
            int e = tid + i * 256;
            int r = e >> 2, c4 = e & 3;
            cp16(sa + (r * LDA_S + c4 * 4) * 4,
                 A + (size_t)(m0 + r) * K + k0 + c4 * 4);
        }
#pragma unroll
        for (int i = 0; i < 2; i++) {
            int e = tid + i * 256;
            int r = e >> 5, c4 = e & 31;
            cp16(sb0 + (r * LDB_D + c4 * 4) * 4,
                 Bi + (size_t)(k0 + r) * N + n0 + c4 * 4);
        }
#pragma unroll
        for (int i = 0; i < 2; i++) {
            int e = tid + i * 256;
            int r = e >> 5, c4 = e & 31;
            cp16(sb1 + (r * LDB_D + c4 * 4) * 4,
                 Bf + (size_t)(k0 + r) * N + n0 + c4 * 4);
        }
        asm volatile("cp.async.commit_group;\n" ::: "memory");
    };

    const int KT = K / BK;
    load_stage(0, 0);
    load_stage(1, 1);
    load_stage(2, 2);

    for (int kt = 0; kt < KT; kt++) {
        const int s = kt & 3;
        if (kt < KT - 2)
            asm volatile("cp.async.wait_group 2;\n" ::: "memory");
        else if (kt == KT - 2)
            asm volatile("cp.async.wait_group 1;\n" ::: "memory");
        else
            asm volatile("cp.async.wait_group 0;\n" ::: "memory");
        __syncthreads();

        const float* sA  = smem + s * STG_D;
        const float* sB0 = sA + A_FLOATS;
        const float* sB1 = sB0 + BD_FLOATS;

#pragma unroll
        for (int kk = 0; kk < 2; kk++) {
            uint32_t af[4][4], bfi[4][2], bff[4][2];
#pragma unroll
            for (int im = 0; im < 4; im++) {
                int r0 = wm * 64 + im * 16 + gid;
                int c0 = kk * 8 + tig;
                af[im][0] = __float_as_uint(sA[r0 * LDA_S + c0]);
                af[im][1] = __float_as_uint(sA[(r0 + 8) * LDA_S + c0]);
                af[im][2] = __float_as_uint(sA[r0 * LDA_S + c0 + 4]);
                af[im][3] = __float_as_uint(sA[(r0 + 8) * LDA_S + c0 + 4]);
            }
#pragma unroll
            for (int in = 0; in < 4; in++) {
                int n = wn * 32 + in * 8 + gid;
                int k = kk * 8 + tig;
                bfi[in][0] = __float_as_uint(sB0[k * LDB_D + n]);
                bfi[in][1] = __float_as_uint(sB0[(k + 4) * LDB_D + n]);
                bff[in][0] = __float_as_uint(sB1[k * LDB_D + n]);
                bff[in][1] = __float_as_uint(sB1[(k + 4) * LDB_D + n]);
            }
#pragma unroll
            for (int im = 0; im < 4; im++)
#pragma unroll
                for (int in = 0; in < 4; in++) {
                    mma1688(acci[im][in], af[im], bfi[in]);
                    mma1688(accf[im][in], af[im], bff[in]);
                }
        }

        if (kt + 3 < KT)
            load_stage(kt + 3, (kt + 3) & 3);
    }

    // Epilogue: a = sigmoid(f); inp = silu(i) * (1 - a)
#pragma unroll
    for (int im = 0; im < 4; im++) {
        int row0 = m0 + wm * 64 + im * 16 + gid;
#pragma unroll
        for (int in = 0; in < 4; in++) {
            int col = n0 + wn * 32 + in * 8 + 2 * tig;
#pragma unroll
            for (int h = 0; h < 2; h++) {          // h=0: row0, h=1: row0+8
                size_t off = (size_t)(row0 + 8 * h) * N + col;
                float fv0 = accf[im][in][2 * h], fv1 = accf[im][in][2 * h + 1];
                float iv0 = acci[im][in][2 * h], iv1 = acci[im][in][2 * h + 1];
                float a0 = sigm(fv0), a1 = sigm(fv1);
                float p0 = iv0 * sigm(iv0) * (1.0f - a0);
                float p1 = iv1 * sigm(iv1) * (1.0f - a1);
                *reinterpret_cast<float2*>(&aOut[off])   = make_float2(a0, a1);
                *reinterpret_cast<float2*>(&inpOut[off]) = make_float2(p0, p1);
            }
        }
    }
}

// ---------------------------------------------------------------------------
// Wide GEMM: C = A * B, CTA 128x256, warp 64x64. If GATE, C = silu(A*B).
// ---------------------------------------------------------------------------
__global__ __launch_bounds__(256, 1)
void gemm_wide(const float* __restrict__ A, const float* __restrict__ Bw,
               float* __restrict__ C, int M, int N, int K, int gate)
{
    extern __shared__ float smem[];

    const int tid  = threadIdx.x;
    const int warp = tid >> 5;
    const int lane = tid & 31;
    const int wm   = warp >> 2;
    const int wn   = warp & 3;
    const int gid  = lane >> 2;
    const int tig  = lane & 3;
    const int m0   = blockIdx.y * 128;
    const int n0   = blockIdx.x * 256;

    float acc[4][8][4];
#pragma unroll
    for (int i = 0; i < 4; i++)
#pragma unroll
        for (int j = 0; j < 8; j++)
#pragma unroll
            for (int r = 0; r < 4; r++) acc[i][j][r] = 0.0f;

    const uint32_t smem_b = (uint32_t)__cvta_generic_to_shared(smem);

    auto load_stage = [&](int kt, int s) {
        const int k0 = kt * BK;
        const uint32_t sa = smem_b + s * STG_W * 4;
        const uint32_t sb = sa + A_FLOATS * 4;
#pragma unroll
        for (int i = 0; i < 2; i++) {
            int e = tid + i * 256;
            int r = e >> 2, c4 = e & 3;
            cp16(sa + (r * LDA_S + c4 * 4) * 4,
                 A + (size_t)(m0 + r) * K + k0 + c4 * 4);
        }
#pragma unroll
        for (int i = 0; i < 4; i++) {
            int e = tid + i * 256;
            int r = e >> 6, c4 = e & 63;
            cp16(sb + (r * LDB_W + c4 * 4) * 4,
                 Bw + (size_t)(k0 + r) * N + n0 + c4 * 4);
        }
        asm volatile("cp.async.commit_group;\n" ::: "memory");
    };

    const int KT = K / BK;
    load_stage(0, 0);
    load_stage(1, 1);
    load_stage(2, 2);

    for (int kt = 0; kt < KT; kt++) {
        const int s = kt & 3;
        if (kt < KT - 2)
            asm volatile("cp.async.wait_group 2;\n" ::: "memory");
        else if (kt == KT - 2)
            asm volatile("cp.async.wait_group 1;\n" ::: "memory");
        else
            asm volatile("cp.async.wait_group 0;\n" ::: "memory");
        __syncthreads();

        const float* sA = smem + s * STG_W;
        const float* sB = sA + A_FLOATS;

#pragma unroll
        for (int kk = 0; kk < 2; kk++) {
            uint32_t af[4][4], bf[8][2];
#pragma unroll
            for (int im = 0; im < 4; im++) {
                int r0 = wm * 64 + im * 16 + gid;
                int c0 = kk * 8 + tig;
                af[im][0] = __float_as_uint(sA[r0 * LDA_S + c0]);
                af[im][1] = __float_as_uint(sA[(r0 + 8) * LDA_S + c0]);
                af[im][2] = __float_as_uint(sA[r0 * LDA_S + c0 + 4]);
                af[im][3] = __float_as_uint(sA[(r0 + 8) * LDA_S + c0 + 4]);
            }
#pragma unroll
            for (int in = 0; in < 8; in++) {
                int n = wn * 64 + in * 8 + gid;
                int k = kk * 8 + tig;
                bf[in][0] = __float_as_uint(sB[k * LDB_W + n]);
                bf[in][1] = __float_as_uint(sB[(k + 4) * LDB_W + n]);
            }
#pragma unroll
            for (int im = 0; im < 4; im++)
#pragma unroll
                for (int in = 0; in < 8; in++)
                    mma1688(acc[im][in], af[im], bf[in]);
        }

        if (kt + 3 < KT)
            load_stage(kt + 3, (kt + 3) & 3);
    }

#pragma unroll
    for (int im = 0; im < 4; im++) {
        int row0 = m0 + wm * 64 + im * 16 + gid;
#pragma unroll
        for (int in = 0; in < 8; in++) {
            int col = n0 + wn * 64 + in * 8 + 2 * tig;
#pragma unroll
            for (int h = 0; h < 2; h++) {
                float v0 = acc[im][in][2 * h], v1 = acc[im][in][2 * h + 1];
                if (gate) { v0 *= sigm(v0); v1 *= sigm(v1); }
                *reinterpret_cast<float2*>(
                    &C[(size_t)(row0 + 8 * h) * N + col]) = make_float2(v0, v1);
            }
        }
    }
}

// ---------------------------------------------------------------------------
// Parallel scan (3 passes), pure fma now: h_t = a*h + inp
// ---------------------------------------------------------------------------
__global__ void scan_pass1(const float* __restrict__ aA,
                           const float* __restrict__ inpA,
                           float* __restrict__ o,
                           float* __restrict__ cA,
                           float* __restrict__ cH)
{
    const int blocksPerBC = Dd / 256;
    int d  = (blockIdx.x % blocksPerBC) * 256 + threadIdx.x;
    int bc = blockIdx.x / blocksPerBC;
    int b  = bc / NC;
    int c  = bc % NC;
    size_t base = ((size_t)b * Tt + (size_t)c * CH) * Dd + d;

    float h = 0.0f, pa = 1.0f;
#pragma unroll 4
    for (int t = 0; t < CH; t++) {
        size_t idx = base + (size_t)t * Dd;
        float a = aA[idx];
        h  = fmaf(a, h, inpA[idx]);
        pa *= a;
        o[idx] = h;
    }
    cA[(size_t)bc * Dd + d] = pa;
    cH[(size_t)bc * Dd + d] = h;
}

__global__ void scan_pass2(const float* __restrict__ cA,
                           const float* __restrict__ cH,
                           float* __restrict__ cIn)
{
    int ch = blockIdx.x * blockDim.x + threadIdx.x;
    int b  = ch / Dd;
    int d  = ch - b * Dd;
    float H = 0.0f;
#pragma unroll
    for (int c = 0; c < NC; c++) {
        size_t idx = ((size_t)b * NC + c) * Dd + d;
        cIn[idx] = H;
        H = fmaf(cA[idx], H, cH[idx]);
    }
}

__global__ void scan_pass3(const float* __restrict__ aA,
                           const float* __restrict__ cIn,
                           float* __restrict__ o)
{
    const int blocksPerBC = Dd / 256;
    int d  = (blockIdx.x % blocksPerBC) * 256 + threadIdx.x;
    int bc = blockIdx.x / blocksPerBC;
    int b  = bc / NC;
    int c  = bc % NC;
    if (c == 0) return;

    float pa = cIn[(size_t)bc * Dd + d];
    size_t base = ((size_t)b * Tt + (size_t)c * CH) * Dd + d;
#pragma unroll 4
    for (int t = 0; t < CH; t++) {
        size_t idx = base + (size_t)t * Dd;
        pa *= aA[idx];
        o[idx] += pa;
    }
}

// ---------------------------------------------------------------------------
// u = tf32_round( RMSNorm(o) * w * gsw ), gsw = silu(g) precomputed
// ---------------------------------------------------------------------------
__global__ __launch_bounds__(256)
void norm_gate_kernel(const float* __restrict__ o,
                      const float* __restrict__ gsw,
                      const float* __restrict__ w,
                      float* __restrict__ u)
{
    int row = blockIdx.x;
    const float4* op = reinterpret_cast<const float4*>(o + (size_t)row * Dd);
    const float4* gp = reinterpret_cast<const float4*>(gsw + (size_t)row * Dd);
    const float4* wp = reinterpret_cast<const float4*>(w);
    float4*       up = reinterpret_cast<float4*>(u + (size_t)row * Dd);

    float4 va[2];
    float s = 0.0f;
#pragma unroll
    for (int i = 0; i < 2; i++) {
        va[i] = op[threadIdx.x + i * 256];
        s += va[i].x * va[i].x + va[i].y * va[i].y
           + va[i].z * va[i].z + va[i].w * va[i].w;
    }
#pragma unroll
    for (int k = 16; k > 0; k >>= 1)
        s += __shfl_xor_sync(0xffffffffu, s, k);
    __shared__ float red[8];
    if ((threadIdx.x & 31) == 0) red[threadIdx.x >> 5] = s;
    __syncthreads();
    if (threadIdx.x < 8) {
        float v = red[threadIdx.x];
#pragma unroll
        for (int k = 4; k > 0; k >>= 1)
            v += __shfl_xor_sync(0xffu, v, k);
        if (threadIdx.x == 0) red[0] = v;
    }
    __syncthreads();
    float r = rsqrtf(red[0] * (1.0f / Dd) + EPS);

#pragma unroll
    for (int i = 0; i < 2; i++) {
        float4 vg = gp[threadIdx.x + i * 256];
        float4 vw = wp[threadIdx.x + i * 256];
        float4 out;
        out.x = tf32r(va[i].x * r * vw.x * vg.x);
        out.y = tf32r(va[i].y * r * vw.y * vg.y);
        out.z = tf32r(va[i].z * r * vw.z * vg.z);
        out.w = tf32r(va[i].w * r * vw.w * vg.w);
        up[threadIdx.x + i * 256] = out;
    }
}

// ---------------------------------------------------------------------------
extern "C" void kernel_launch(void* const* d_in, const int* in_sizes, int n_in,
                              void* d_out, int out_size)
{
    const float* x  = (const float*)d_in[0];
    const float* Wi = (const float*)d_in[1];
    const float* Wf = (const float*)d_in[2];
    const float* Wg = (const float*)d_in[3];
    const float* Wo = (const float*)d_in[4];
    const float* gw = (const float*)d_in[5];
    float* out = (float*)d_out;

    float *aA, *inpA, *gg, *o, *u, *xr, *wr, *cA, *cH, *cIn;
    cudaGetSymbolAddress((void**)&aA,   g_a);
    cudaGetSymbolAddress((void**)&inpA, g_inp);
    cudaGetSymbolAddress((void**)&gg,   g_gg);
    cudaGetSymbolAddress((void**)&o,    g_o);
    cudaGetSymbolAddress((void**)&u,    g_u);
    cudaGetSymbolAddress((void**)&xr,   g_xr);
    cudaGetSymbolAddress((void**)&wr,   g_wr);
    cudaGetSymbolAddress((void**)&cA,   g_cA);
    cudaGetSymbolAddress((void**)&cH,   g_cH);
    cudaGetSymbolAddress((void**)&cIn,  g_cIn);

    cudaFuncSetAttribute(gemm_if,
                         cudaFuncAttributeMaxDynamicSharedMemorySize, SMEM_D);
    cudaFuncSetAttribute(gemm_wide,
                         cudaFuncAttributeMaxDynamicSharedMemorySize, SMEM_W);

    const size_t WSZ = (size_t)Dd * Dd;

    {
        int n4x = (int)((size_t)BT * Dd / 4);
        int n4w = (int)(WSZ / 4);
        round_tf32_kernel<<<n4x / 256, 256>>>(x,  xr, n4x);
        round_tf32_kernel<<<n4w / 256, 256>>>(Wi, wr + 0 * WSZ, n4w);
        round_tf32_kernel<<<n4w / 256, 256>>>(Wf, wr + 1 * WSZ, n4w);
        round_tf32_kernel<<<n4w / 256, 256>>>(Wg, wr + 2 * WSZ, n4w);
        round_tf32_kernel<<<n4w / 256, 256>>>(Wo, wr + 3 * WSZ, n4w);
    }

    // Fused i+f GEMM + gates
    {
        dim3 grid(Dd / 128, BT / 128);   // (16, 128)
        gemm_if<<<grid, 256, SMEM_D>>>(xr, wr + 0 * WSZ, wr + 1 * WSZ,
                                       aA, inpA, BT, Dd, Dd);
    }
    // g GEMM (+ silu gate fused)
    {
        dim3 grid(Dd / 256, BT / 128);   // (8, 128)
        gemm_wide<<<grid, 256, SMEM_W>>>(xr, wr + 2 * WSZ, gg, BT, Dd, Dd, 1);
    }

    const int scanBlocks = Bb * NC * (Dd / 256);   // 1024
    scan_pass1<<<scanBlocks, 256>>>(aA, inpA, o, cA, cH);
    scan_pass2<<<(Bb * Dd) / 256, 256>>>(cA, cH, cIn);
    scan_pass3<<<scanBlocks, 256>>>(aA, cIn, o);

    norm_gate_kernel<<<BT, 256>>>(o, gg, gw, u);

    // Output GEMM
    {
        dim3 grid(Dd / 256, BT / 128);
        gemm_wide<<<grid, 256, SMEM_W>>>(u, wr + 3 * WSZ, out, BT, Dd, Dd, 0);
    }
}

// round 6
// speedup vs baseline: 1.0113x; 1.0113x over previous
#include <cuda_runtime.h>
#include <math.h>
#include <stdint.h>

// Problem shape (fixed for this dataset instance)
constexpr int Bb = 4;
constexpr int Tt = 4096;
constexpr int Dd = 2048;
constexpr int BT = Bb * Tt;           // 16384 rows
constexpr float EPS = 1e-5f;

// Scan chunking
constexpr int NC = 32;
constexpr int CH = Tt / NC;           // 128

// GEMM tiling (mma.sync tf32): CTA 128x128, BK=32, 3 stages, 2 CTAs/SM
constexpr int BM = 128;
constexpr int BN = 128;
constexpr int BK = 32;
constexpr int LDA_S = 36;             // padded floats per A row
constexpr int LDB_S = 136;            // padded floats per B row
constexpr int STAGES = 3;
constexpr int A_FLOATS = BM * LDA_S;  // 4608
constexpr int B_FLOATS = BK * LDB_S;  // 4352
constexpr int STG_FLOATS = A_FLOATS + B_FLOATS;       // 8960
constexpr int GEMM_SMEM = STAGES * STG_FLOATS * 4;    // 107520 bytes

// Scratch (device globals — no allocation allowed)
__device__ float g_a   [(size_t)BT * Dd];      // sigmoid(f)
__device__ float g_si  [(size_t)BT * Dd];      // silu(i)
__device__ float g_gg  [(size_t)BT * Dd];      // silu(g)
__device__ float g_o   [(size_t)BT * Dd];
__device__ float g_u   [(size_t)BT * Dd];
__device__ float g_xr  [(size_t)BT * Dd];      // tf32-rounded x
__device__ float g_wr  [(size_t)4 * Dd * Dd];  // tf32-rounded weights [K][N]
__device__ float g_cA  [(size_t)Bb * NC * Dd];
__device__ float g_cH  [(size_t)Bb * NC * Dd];
__device__ float g_cIn [(size_t)Bb * NC * Dd];

// ---------------------------------------------------------------------------
__device__ __forceinline__ float tf32r(float x) {
    uint32_t u;
    asm("cvt.rna.tf32.f32 %0, %1;" : "=r"(u) : "f"(x));
    return __uint_as_float(u);
}

__device__ __forceinline__ void cp16(uint32_t dst, const void* src) {
    asm volatile("cp.async.cg.shared.global [%0], [%1], 16;\n" :: "r"(dst), "l"(src));
}

__device__ __forceinline__ void mma1688(float* d, const uint32_t* a, const uint32_t* b) {
    asm volatile(
        "mma.sync.aligned.m16n8k8.row.col.f32.tf32.tf32.f32 "
        "{%0,%1,%2,%3}, {%4,%5,%6,%7}, {%8,%9}, {%0,%1,%2,%3};"
        : "+f"(d[0]), "+f"(d[1]), "+f"(d[2]), "+f"(d[3])
        : "r"(a[0]), "r"(a[1]), "r"(a[2]), "r"(a[3]), "r"(b[0]), "r"(b[1]));
}

__device__ __forceinline__ float sigm(float v) { return 1.0f / (1.0f + __expf(-v)); }

// ---------------------------------------------------------------------------
__global__ void round_tf32_kernel(const float* __restrict__ in,
                                  float* __restrict__ out, int n4)
{
    int i = blockIdx.x * blockDim.x + threadIdx.x;
    if (i < n4) {
        float4 v = reinterpret_cast<const float4*>(in)[i];
        v.x = tf32r(v.x); v.y = tf32r(v.y); v.z = tf32r(v.z); v.w = tf32r(v.w);
        reinterpret_cast<float4*>(out)[i] = v;
    }
}

// ---------------------------------------------------------------------------
// C[M,N] = act(A[M,K] * B[K,N]); A row-major K-contig, B row-major N-contig.
// mode: 0 = identity, 1 = sigmoid, 2 = silu.
// BK=32, 3-stage cp.async ring, 8 warps (2m x 4n), warp 64x32.
// ---------------------------------------------------------------------------
__global__ __launch_bounds__(256, 2)
void gemm_mma(const float* __restrict__ A, const float* __restrict__ Bw,
              float* __restrict__ C, int M, int N, int K, int mode)
{
    extern __shared__ float smem[];

    const int tid  = threadIdx.x;
    const int warp = tid >> 5;
    const int lane = tid & 31;
    const int wm   = warp >> 2;          // 0..1
    const int wn   = warp & 3;           // 0..3
    const int gid  = lane >> 2;          // 0..7
    const int tig  = lane & 3;           // 0..3
    const int m0   = blockIdx.y * BM;
    const int n0   = blockIdx.x * BN;

    float acc[4][4][4];
#pragma unroll
    for (int i = 0; i < 4; i++)
#pragma unroll
        for (int j = 0; j < 4; j++)
#pragma unroll
            for (int r = 0; r < 4; r++)
                acc[i][j][r] = 0.0f;

    const uint32_t smem_b = (uint32_t)__cvta_generic_to_shared(smem);

    auto load_stage = [&](int kt, int s) {
        const int k0 = kt * BK;
        const uint32_t sa = smem_b + s * STG_FLOATS * 4;
        const uint32_t sb = sa + A_FLOATS * 4;
        // A: 128 rows x 8 float4 = 1024
#pragma unroll
        for (int i = 0; i < 4; i++) {
            int e = tid + i * 256;
            int r = e >> 3, c4 = e & 7;
            cp16(sa + (r * LDA_S + c4 * 4) * 4,
                 A + (size_t)(m0 + r) * K + k0 + c4 * 4);
        }
        // B: 32 rows x 32 float4 = 1024
#pragma unroll
        for (int i = 0; i < 4; i++) {
            int e = tid + i * 256;
            int r = e >> 5, c4 = e & 31;
            cp16(sb + (r * LDB_S + c4 * 4) * 4,
                 Bw + (size_t)(k0 + r) * N + n0 + c4 * 4);
        }
        asm volatile("cp.async.commit_group;\n" ::: "memory");
    };

    const int KT = K / BK;               // 64
    load_stage(0, 0);
    load_stage(1, 1);

    for (int kt = 0; kt < KT; kt++) {
        if (kt < KT - 1)
            asm volatile("cp.async.wait_group 1;\n" ::: "memory");
        else
            asm volatile("cp.async.wait_group 0;\n" ::: "memory");
        __syncthreads();

        // Prefetch stage kt+2 into the buffer freed by iteration kt-1
        if (kt + 2 < KT)
            load_stage(kt + 2, (kt + 2) % 3);

        const float* sA = smem + (kt % 3) * STG_FLOATS;
        const float* sB = sA + A_FLOATS;

#pragma unroll
        for (int kk = 0; kk < 4; kk++) {             // four k8 steps
            uint32_t af[4][4];
            uint32_t bf[4][2];
#pragma unroll
            for (int im = 0; im < 4; im++) {
                int r0 = wm * 64 + im * 16 + gid;
                int c0 = kk * 8 + tig;
                af[im][0] = __float_as_uint(sA[r0 * LDA_S + c0]);
                af[im][1] = __float_as_uint(sA[(r0 + 8) * LDA_S + c0]);
                af[im][2] = __float_as_uint(sA[r0 * LDA_S + c0 + 4]);
                af[im][3] = __float_as_uint(sA[(r0 + 8) * LDA_S + c0 + 4]);
            }
#pragma unroll
            for (int in = 0; in < 4; in++) {
                int n = wn * 32 + in * 8 + gid;
                int k = kk * 8 + tig;
                bf[in][0] = __float_as_uint(sB[k * LDB_S + n]);
                bf[in][1] = __float_as_uint(sB[(k + 4) * LDB_S + n]);
            }
#pragma unroll
            for (int im = 0; im < 4; im++)
#pragma unroll
                for (int in = 0; in < 4; in++)
                    mma1688(acc[im][in], af[im], bf[in]);
        }
    }

    // Epilogue with fused activation
#pragma unroll
    for (int im = 0; im < 4; im++) {
        int row0 = m0 + wm * 64 + im * 16 + gid;
#pragma unroll
        for (int in = 0; in < 4; in++) {
            int col = n0 + wn * 32 + in * 8 + 2 * tig;
#pragma unroll
            for (int h = 0; h < 2; h++) {
                float v0 = acc[im][in][2 * h], v1 = acc[im][in][2 * h + 1];
                if (mode == 1)      { v0 = sigm(v0);      v1 = sigm(v1); }
                else if (mode == 2) { v0 *= sigm(v0);     v1 *= sigm(v1); }
                *reinterpret_cast<float2*>(
                    &C[(size_t)(row0 + 8 * h) * N + col]) = make_float2(v0, v1);
            }
        }
    }
}

// ---------------------------------------------------------------------------
// Parallel scan (3 passes), pure FMA: h_t = a*h + si*(1-a)
// ---------------------------------------------------------------------------
__global__ void scan_pass1(const float* __restrict__ aA,
                           const float* __restrict__ siA,
                           float* __restrict__ o,
                           float* __restrict__ cA,
                           float* __restrict__ cH)
{
    const int blocksPerBC = Dd / 256;            // 8
    int d  = (blockIdx.x % blocksPerBC) * 256 + threadIdx.x;
    int bc = blockIdx.x / blocksPerBC;
    int b  = bc / NC;
    int c  = bc % NC;
    size_t base = ((size_t)b * Tt + (size_t)c * CH) * Dd + d;

    float h = 0.0f, pa = 1.0f;
#pragma unroll 4
    for (int t = 0; t < CH; t++) {
        size_t idx = base + (size_t)t * Dd;
        float a  = aA[idx];
        float in = siA[idx] * (1.0f - a);
        h  = fmaf(a, h, in);
        pa *= a;
        o[idx] = h;
    }
    cA[(size_t)bc * Dd + d] = pa;
    cH[(size_t)bc * Dd + d] = h;
}

__global__ void scan_pass2(const float* __restrict__ cA,
                           const float* __restrict__ cH,
                           float* __restrict__ cIn)
{
    int ch = blockIdx.x * blockDim.x + threadIdx.x;
    int b  = ch / Dd;
    int d  = ch - b * Dd;
    float H = 0.0f;
#pragma unroll
    for (int c = 0; c < NC; c++) {
        size_t idx = ((size_t)b * NC + c) * Dd + d;
        cIn[idx] = H;
        H = fmaf(cA[idx], H, cH[idx]);
    }
}

__global__ void scan_pass3(const float* __restrict__ aA,
                           const float* __restrict__ cIn,
                           float* __restrict__ o)
{
    const int blocksPerBC = Dd / 256;
    int d  = (blockIdx.x % blocksPerBC) * 256 + threadIdx.x;
    int bc = blockIdx.x / blocksPerBC;
    int b  = bc / NC;
    int c  = bc % NC;
    if (c == 0) return;

    float pa = cIn[(size_t)bc * Dd + d];
    size_t base = ((size_t)b * Tt + (size_t)c * CH) * Dd + d;
#pragma unroll 4
    for (int t = 0; t < CH; t++) {
        size_t idx = base + (size_t)t * Dd;
        pa *= aA[idx];
        o[idx] += pa;
    }
}

// ---------------------------------------------------------------------------
// u = tf32_round( RMSNorm(o) * w * gsw ), gsw = silu(g) precomputed
// ---------------------------------------------------------------------------
__global__ __launch_bounds__(256)
void norm_gate_kernel(const float* __restrict__ o,
                      const float* __restrict__ gsw,
                      const float* __restrict__ w,
                      float* __restrict__ u)
{
    int row = blockIdx.x;
    const float4* op = reinterpret_cast<const float4*>(o + (size_t)row * Dd);
    const float4* gp = reinterpret_cast<const float4*>(gsw + (size_t)row * Dd);
    const float4* wp = reinterpret_cast<const float4*>(w);
    float4*       up = reinterpret_cast<float4*>(u + (size_t)row * Dd);

    float4 va[2];
    float s = 0.0f;
#pragma unroll
    for (int i = 0; i < 2; i++) {
        va[i] = op[threadIdx.x + i * 256];
        s += va[i].x * va[i].x + va[i].y * va[i].y
           + va[i].z * va[i].z + va[i].w * va[i].w;
    }
#pragma unroll
    for (int k = 16; k > 0; k >>= 1)
        s += __shfl_xor_sync(0xffffffffu, s, k);
    __shared__ float red[8];
    if ((threadIdx.x & 31) == 0) red[threadIdx.x >> 5] = s;
    __syncthreads();
    if (threadIdx.x < 8) {
        float v = red[threadIdx.x];
#pragma unroll
        for (int k = 4; k > 0; k >>= 1)
            v += __shfl_xor_sync(0xffu, v, k);
        if (threadIdx.x == 0) red[0] = v;
    }
    __syncthreads();
    float r = rsqrtf(red[0] * (1.0f / Dd) + EPS);

#pragma unroll
    for (int i = 0; i < 2; i++) {
        float4 vg = gp[threadIdx.x + i * 256];
        float4 vw = wp[threadIdx.x + i * 256];
        float4 out;
        out.x = tf32r(va[i].x * r * vw.x * vg.x);
        out.y = tf32r(va[i].y * r * vw.y * vg.y);
        out.z = tf32r(va[i].z * r * vw.z * vg.z);
        out.w = tf32r(va[i].w * r * vw.w * vg.w);
        up[threadIdx.x + i * 256] = out;
    }
}

// ---------------------------------------------------------------------------
extern "C" void kernel_launch(void* const* d_in, const int* in_sizes, int n_in,
                              void* d_out, int out_size)
{
    const float* x  = (const float*)d_in[0];
    const float* Wi = (const float*)d_in[1];
    const float* Wf = (const float*)d_in[2];
    const float* Wg = (const float*)d_in[3];
    const float* Wo = (const float*)d_in[4];
    const float* gw = (const float*)d_in[5];
    float* out = (float*)d_out;

    float *aA, *siA, *gg, *o, *u, *xr, *wr, *cA, *cH, *cIn;
    cudaGetSymbolAddress((void**)&aA,  g_a);
    cudaGetSymbolAddress((void**)&siA, g_si);
    cudaGetSymbolAddress((void**)&gg,  g_gg);
    cudaGetSymbolAddress((void**)&o,   g_o);
    cudaGetSymbolAddress((void**)&u,   g_u);
    cudaGetSymbolAddress((void**)&xr,  g_xr);
    cudaGetSymbolAddress((void**)&wr,  g_wr);
    cudaGetSymbolAddress((void**)&cA,  g_cA);
    cudaGetSymbolAddress((void**)&cH,  g_cH);
    cudaGetSymbolAddress((void**)&cIn, g_cIn);

    cudaFuncSetAttribute(gemm_mma,
                         cudaFuncAttributeMaxDynamicSharedMemorySize, GEMM_SMEM);

    const size_t WSZ = (size_t)Dd * Dd;

    // Pre-round x and weights to tf32 (weights stay in native [K][N] layout)
    {
        int n4x = (int)((size_t)BT * Dd / 4);
        int n4w = (int)(WSZ / 4);
        round_tf32_kernel<<<n4x / 256, 256>>>(x,  xr, n4x);
        round_tf32_kernel<<<n4w / 256, 256>>>(Wi, wr + 0 * WSZ, n4w);
        round_tf32_kernel<<<n4w / 256, 256>>>(Wf, wr + 1 * WSZ, n4w);
        round_tf32_kernel<<<n4w / 256, 256>>>(Wg, wr + 2 * WSZ, n4w);
        round_tf32_kernel<<<n4w / 256, 256>>>(Wo, wr + 3 * WSZ, n4w);
    }

    dim3 ggrid(Dd / BN, BT / BM);   // (16, 128)
    dim3 gblk(256);

    // i: silu(i); f: sigmoid(f); g: silu(g)
    gemm_mma<<<ggrid, gblk, GEMM_SMEM>>>(xr, wr + 0 * WSZ, siA, BT, Dd, Dd, 2);
    gemm_mma<<<ggrid, gblk, GEMM_SMEM>>>(xr, wr + 1 * WSZ, aA,  BT, Dd, Dd, 1);
    gemm_mma<<<ggrid, gblk, GEMM_SMEM>>>(xr, wr + 2 * WSZ, gg,  BT, Dd, Dd, 2);

    const int scanBlocks = Bb * NC * (Dd / 256);   // 1024
    scan_pass1<<<scanBlocks, 256>>>(aA, siA, o, cA, cH);
    scan_pass2<<<(Bb * Dd) / 256, 256>>>(cA, cH, cIn);
    scan_pass3<<<scanBlocks, 256>>>(aA, cIn, o);

    norm_gate_kernel<<<BT, 256>>>(o, gg, gw, u);

    // Output GEMM (identity epilogue)
    gemm_mma<<<ggrid, gblk, GEMM_SMEM>>>(u, wr + 3 * WSZ, out, BT, Dd, Dd, 0);
}

// round 7
// speedup vs baseline: 1.0892x; 1.0771x over previous
#include <cuda_runtime.h>
#include <math.h>
#include <stdint.h>

// Problem shape (fixed for this dataset instance)
constexpr int Bb = 4;
constexpr int Tt = 4096;
constexpr int Dd = 2048;
constexpr int BT = Bb * Tt;           // 16384 rows
constexpr float EPS = 1e-5f;

// Scan chunking
constexpr int NC = 32;
constexpr int CH = Tt / NC;           // 128

// GEMM tiling (mma.sync tf32) — round-4 proven config
constexpr int BM = 128;
constexpr int BN = 128;
constexpr int BK = 16;
constexpr int LDA_S = 20;             // padded floats per A row (bank-clean)
constexpr int LDB_S = 136;            // padded floats per B row (bank-clean)
constexpr int STAGES = 4;
constexpr int A_FLOATS = BM * LDA_S;  // 2560
constexpr int B_FLOATS = BK * LDB_S;  // 2176
constexpr int STG_FLOATS = A_FLOATS + B_FLOATS;       // 4736
constexpr int GEMM_SMEM = STAGES * STG_FLOATS * 4;    // 75776 bytes

// Scratch (device globals — no allocation allowed)
__device__ float g_a   [(size_t)BT * Dd];      // sigmoid(f)
__device__ float g_si  [(size_t)BT * Dd];      // silu(i)
__device__ float g_gg  [(size_t)BT * Dd];      // silu(g)
__device__ float g_o   [(size_t)BT * Dd];
__device__ float g_u   [(size_t)BT * Dd];
__device__ float g_xr  [(size_t)BT * Dd];      // tf32-rounded x
__device__ float g_wr  [(size_t)4 * Dd * Dd];  // tf32-rounded weights [K][N]
__device__ float g_cA  [(size_t)Bb * NC * Dd];
__device__ float g_cH  [(size_t)Bb * NC * Dd];
__device__ float g_cIn [(size_t)Bb * NC * Dd];

// ---------------------------------------------------------------------------
__device__ __forceinline__ float tf32r(float x) {
    uint32_t u;
    asm("cvt.rna.tf32.f32 %0, %1;" : "=r"(u) : "f"(x));
    return __uint_as_float(u);
}

__device__ __forceinline__ void cp16(uint32_t dst, const void* src) {
    asm volatile("cp.async.cg.shared.global [%0], [%1], 16;\n" :: "r"(dst), "l"(src));
}

__device__ __forceinline__ void mma1688(float* d, const uint32_t* a, const uint32_t* b) {
    asm volatile(
        "mma.sync.aligned.m16n8k8.row.col.f32.tf32.tf32.f32 "
        "{%0,%1,%2,%3}, {%4,%5,%6,%7}, {%8,%9}, {%0,%1,%2,%3};"
        : "+f"(d[0]), "+f"(d[1]), "+f"(d[2]), "+f"(d[3])
        : "r"(a[0]), "r"(a[1]), "r"(a[2]), "r"(a[3]), "r"(b[0]), "r"(b[1]));
}

__device__ __forceinline__ float sigm(float v) { return 1.0f / (1.0f + __expf(-v)); }

// ---------------------------------------------------------------------------
__global__ void round_tf32_kernel(const float* __restrict__ in,
                                  float* __restrict__ out, int n4)
{
    int i = blockIdx.x * blockDim.x + threadIdx.x;
    if (i < n4) {
        float4 v = reinterpret_cast<const float4*>(in)[i];
        v.x = tf32r(v.x); v.y = tf32r(v.y); v.z = tf32r(v.z); v.w = tf32r(v.w);
        reinterpret_cast<float4*>(out)[i] = v;
    }
}

// ---------------------------------------------------------------------------
// C[M,N] = act(A[M,K] * B[K,N]); A row-major K-contig, B row-major N-contig.
// mode: 0 = identity, 1 = sigmoid, 2 = silu.
// Round-4 pipeline: BK=16, 4-stage cp.async, load-after-compute, 2 CTAs/SM.
// ---------------------------------------------------------------------------
__global__ __launch_bounds__(256, 2)
void gemm_mma(const float* __restrict__ A, const float* __restrict__ Bw,
              float* __restrict__ C, int M, int N, int K, int mode)
{
    extern __shared__ float smem[];

    const int tid  = threadIdx.x;
    const int warp = tid >> 5;
    const int lane = tid & 31;
    const int wm   = warp >> 2;          // 0..1
    const int wn   = warp & 3;           // 0..3
    const int gid  = lane >> 2;          // 0..7
    const int tig  = lane & 3;           // 0..3
    const int m0   = blockIdx.y * BM;
    const int n0   = blockIdx.x * BN;

    float acc[4][4][4];
#pragma unroll
    for (int i = 0; i < 4; i++)
#pragma unroll
        for (int j = 0; j < 4; j++)
#pragma unroll
            for (int r = 0; r < 4; r++)
                acc[i][j][r] = 0.0f;

    const uint32_t smem_b = (uint32_t)__cvta_generic_to_shared(smem);

    auto load_stage = [&](int kt, int s) {
        const int k0 = kt * BK;
        const uint32_t sa = smem_b + s * STG_FLOATS * 4;
        const uint32_t sb = sa + A_FLOATS * 4;
        // A: 128 rows x 4 float4
#pragma unroll
        for (int i = 0; i < 2; i++) {
            int e = tid + i * 256;
            int r = e >> 2, c4 = e & 3;
            cp16(sa + (r * LDA_S + c4 * 4) * 4,
                 A + (size_t)(m0 + r) * K + k0 + c4 * 4);
        }
        // B: 16 rows x 32 float4
#pragma unroll
        for (int i = 0; i < 2; i++) {
            int e = tid + i * 256;
            int r = e >> 5, c4 = e & 31;
            cp16(sb + (r * LDB_S + c4 * 4) * 4,
                 Bw + (size_t)(k0 + r) * N + n0 + c4 * 4);
        }
        asm volatile("cp.async.commit_group;\n" ::: "memory");
    };

    const int KT = K / BK;               // 128
    load_stage(0, 0);
    load_stage(1, 1);
    load_stage(2, 2);

    for (int kt = 0; kt < KT; kt++) {
        const int s = kt & 3;
        if (kt < KT - 2)
            asm volatile("cp.async.wait_group 2;\n" ::: "memory");
        else if (kt == KT - 2)
            asm volatile("cp.async.wait_group 1;\n" ::: "memory");
        else
            asm volatile("cp.async.wait_group 0;\n" ::: "memory");
        __syncthreads();

        const float* sA = smem + s * STG_FLOATS;
        const float* sB = sA + A_FLOATS;

#pragma unroll
        for (int kk = 0; kk < 2; kk++) {             // two k8 steps
            uint32_t af[4][4];
            uint32_t bf[4][2];
#pragma unroll
            for (int im = 0; im < 4; im++) {
                int r0 = wm * 64 + im * 16 + gid;
                int c0 = kk * 8 + tig;
                af[im][0] = __float_as_uint(sA[r0 * LDA_S + c0]);
                af[im][1] = __float_as_uint(sA[(r0 + 8) * LDA_S + c0]);
                af[im][2] = __float_as_uint(sA[r0 * LDA_S + c0 + 4]);
                af[im][3] = __float_as_uint(sA[(r0 + 8) * LDA_S + c0 + 4]);
            }
#pragma unroll
            for (int in = 0; in < 4; in++) {
                int n = wn * 32 + in * 8 + gid;
                int k = kk * 8 + tig;
                bf[in][0] = __float_as_uint(sB[k * LDB_S + n]);
                bf[in][1] = __float_as_uint(sB[(k + 4) * LDB_S + n]);
            }
#pragma unroll
            for (int im = 0; im < 4; im++)
#pragma unroll
                for (int in = 0; in < 4; in++)
                    mma1688(acc[im][in], af[im], bf[in]);
        }

        // Issue next load AFTER compute (round-4 proven ordering)
        if (kt + 3 < KT)
            load_stage(kt + 3, (kt + 3) & 3);
    }

    // Epilogue with fused activation
#pragma unroll
    for (int im = 0; im < 4; im++) {
        int row0 = m0 + wm * 64 + im * 16 + gid;
#pragma unroll
        for (int in = 0; in < 4; in++) {
            int col = n0 + wn * 32 + in * 8 + 2 * tig;
#pragma unroll
            for (int h = 0; h < 2; h++) {
                float v0 = acc[im][in][2 * h], v1 = acc[im][in][2 * h + 1];
                if (mode == 1)      { v0 = sigm(v0);  v1 = sigm(v1); }
                else if (mode == 2) { v0 *= sigm(v0); v1 *= sigm(v1); }
                *reinterpret_cast<float2*>(
                    &C[(size_t)(row0 + 8 * h) * N + col]) = make_float2(v0, v1);
            }
        }
    }
}

// ---------------------------------------------------------------------------
// Parallel scan (3 passes), pure FMA: h_t = a*h + si*(1-a)
// ---------------------------------------------------------------------------
__global__ void scan_pass1(const float* __restrict__ aA,
                           const float* __restrict__ siA,
                           float* __restrict__ o,
                           float* __restrict__ cA,
                           float* __restrict__ cH)
{
    const int blocksPerBC = Dd / 256;            // 8
    int d  = (blockIdx.x % blocksPerBC) * 256 + threadIdx.x;
    int bc = blockIdx.x / blocksPerBC;
    int b  = bc / NC;
    int c  = bc % NC;
    size_t base = ((size_t)b * Tt + (size_t)c * CH) * Dd + d;

    float h = 0.0f, pa = 1.0f;
#pragma unroll 4
    for (int t = 0; t < CH; t++) {
        size_t idx = base + (size_t)t * Dd;
        float a  = aA[idx];
        float in = siA[idx] * (1.0f - a);
        h  = fmaf(a, h, in);
        pa *= a;
        o[idx] = h;
    }
    cA[(size_t)bc * Dd + d] = pa;
    cH[(size_t)bc * Dd + d] = h;
}

__global__ void scan_pass2(const float* __restrict__ cA,
                           const float* __restrict__ cH,
                           float* __restrict__ cIn)
{
    int ch = blockIdx.x * blockDim.x + threadIdx.x;
    int b  = ch / Dd;
    int d  = ch - b * Dd;
    float H = 0.0f;
#pragma unroll
    for (int c = 0; c < NC; c++) {
        size_t idx = ((size_t)b * NC + c) * Dd + d;
        cIn[idx] = H;
        H = fmaf(cA[idx], H, cH[idx]);
    }
}

__global__ void scan_pass3(const float* __restrict__ aA,
                           const float* __restrict__ cIn,
                           float* __restrict__ o)
{
    const int blocksPerBC = Dd / 256;
    int d  = (blockIdx.x % blocksPerBC) * 256 + threadIdx.x;
    int bc = blockIdx.x / blocksPerBC;
    int b  = bc / NC;
    int c  = bc % NC;
    if (c == 0) return;

    float pa = cIn[(size_t)bc * Dd + d];
    size_t base = ((size_t)b * Tt + (size_t)c * CH) * Dd + d;
#pragma unroll 4
    for (int t = 0; t < CH; t++) {
        size_t idx = base + (size_t)t * Dd;
        pa *= aA[idx];
        o[idx] += pa;
    }
}

// ---------------------------------------------------------------------------
// u = tf32_round( RMSNorm(o) * w * gsw ), gsw = silu(g) precomputed
// ---------------------------------------------------------------------------
__global__ __launch_bounds__(256)
void norm_gate_kernel(const float* __restrict__ o,
                      const float* __restrict__ gsw,
                      const float* __restrict__ w,
                      float* __restrict__ u)
{
    int row = blockIdx.x;
    const float4* op = reinterpret_cast<const float4*>(o + (size_t)row * Dd);
    const float4* gp = reinterpret_cast<const float4*>(gsw + (size_t)row * Dd);
    const float4* wp = reinterpret_cast<const float4*>(w);
    float4*       up = reinterpret_cast<float4*>(u + (size_t)row * Dd);

    float4 va[2];
    float s = 0.0f;
#pragma unroll
    for (int i = 0; i < 2; i++) {
        va[i] = op[threadIdx.x + i * 256];
        s += va[i].x * va[i].x + va[i].y * va[i].y
           + va[i].z * va[i].z + va[i].w * va[i].w;
    }
#pragma unroll
    for (int k = 16; k > 0; k >>= 1)
        s += __shfl_xor_sync(0xffffffffu, s, k);
    __shared__ float red[8];
    if ((threadIdx.x & 31) == 0) red[threadIdx.x >> 5] = s;
    __syncthreads();
    if (threadIdx.x < 8) {
        float v = red[threadIdx.x];
#pragma unroll
        for (int k = 4; k > 0; k >>= 1)
            v += __shfl_xor_sync(0xffu, v, k);
        if (threadIdx.x == 0) red[0] = v;
    }
    __syncthreads();
    float r = rsqrtf(red[0] * (1.0f / Dd) + EPS);

#pragma unroll
    for (int i = 0; i < 2; i++) {
        float4 vg = gp[threadIdx.x + i * 256];
        float4 vw = wp[threadIdx.x + i * 256];
        float4 out;
        out.x = tf32r(va[i].x * r * vw.x * vg.x);
        out.y = tf32r(va[i].y * r * vw.y * vg.y);
        out.z = tf32r(va[i].z * r * vw.z * vg.z);
        out.w = tf32r(va[i].w * r * vw.w * vg.w);
        up[threadIdx.x + i * 256] = out;
    }
}

// ---------------------------------------------------------------------------
extern "C" void kernel_launch(void* const* d_in, const int* in_sizes, int n_in,
                              void* d_out, int out_size)
{
    const float* x  = (const float*)d_in[0];
    const float* Wi = (const float*)d_in[1];
    const float* Wf = (const float*)d_in[2];
    const float* Wg = (const float*)d_in[3];
    const float* Wo = (const float*)d_in[4];
    const float* gw = (const float*)d_in[5];
    float* out = (float*)d_out;

    float *aA, *siA, *gg, *o, *u, *xr, *wr, *cA, *cH, *cIn;
    cudaGetSymbolAddress((void**)&aA,  g_a);
    cudaGetSymbolAddress((void**)&siA, g_si);
    cudaGetSymbolAddress((void**)&gg,  g_gg);
    cudaGetSymbolAddress((void**)&o,   g_o);
    cudaGetSymbolAddress((void**)&u,   g_u);
    cudaGetSymbolAddress((void**)&xr,  g_xr);
    cudaGetSymbolAddress((void**)&wr,  g_wr);
    cudaGetSymbolAddress((void**)&cA,  g_cA);
    cudaGetSymbolAddress((void**)&cH,  g_cH);
    cudaGetSymbolAddress((void**)&cIn, g_cIn);

    cudaFuncSetAttribute(gemm_mma,
                         cudaFuncAttributeMaxDynamicSharedMemorySize, GEMM_SMEM);

    const size_t WSZ = (size_t)Dd * Dd;

    // Pre-round x and weights to tf32 (weights stay in native [K][N] layout)
    {
        int n4x = (int)((size_t)BT * Dd / 4);
        int n4w = (int)(WSZ / 4);
        round_tf32_kernel<<<n4x / 256, 256>>>(x,  xr, n4x);
        round_tf32_kernel<<<n4w / 256, 256>>>(Wi, wr + 0 * WSZ, n4w);
        round_tf32_kernel<<<n4w / 256, 256>>>(Wf, wr + 1 * WSZ, n4w);
        round_tf32_kernel<<<n4w / 256, 256>>>(Wg, wr + 2 * WSZ, n4w);
        round_tf32_kernel<<<n4w / 256, 256>>>(Wo, wr + 3 * WSZ, n4w);
    }

    dim3 ggrid(Dd / BN, BT / BM);   // (16, 128)
    dim3 gblk(256);

    // i: silu(i); f: sigmoid(f); g: silu(g)
    gemm_mma<<<ggrid, gblk, GEMM_SMEM>>>(xr, wr + 0 * WSZ, siA, BT, Dd, Dd, 2);
    gemm_mma<<<ggrid, gblk, GEMM_SMEM>>>(xr, wr + 1 * WSZ, aA,  BT, Dd, Dd, 1);
    gemm_mma<<<ggrid, gblk, GEMM_SMEM>>>(xr, wr + 2 * WSZ, gg,  BT, Dd, Dd, 2);

    const int scanBlocks = Bb * NC * (Dd / 256);   // 1024
    scan_pass1<<<scanBlocks, 256>>>(aA, siA, o, cA, cH);
    scan_pass2<<<(Bb * Dd) / 256, 256>>>(cA, cH, cIn);
    scan_pass3<<<scanBlocks, 256>>>(aA, cIn, o);

    norm_gate_kernel<<<BT, 256>>>(o, gg, gw, u);

    // Output GEMM (identity epilogue)
    gemm_mma<<<ggrid, gblk, GEMM_SMEM>>>(u, wr + 3 * WSZ, out, BT, Dd, Dd, 0);
}